// round 2
// baseline (speedup 1.0000x reference)
#include <cuda_runtime.h>
#include <math.h>

typedef unsigned long long u64;

#define BB 16
#define TT 1024
#define HH 512
#define G4 2048
#define KK 512
#define NB 128

// ---------------- device-global scratch (no allocations allowed) ----------------
__device__ __align__(16) float g_gx[BB * TT * G4];   // 128 MB
__device__ __align__(16) float g_y [BB * TT * HH];   // 32 MB
__device__ __align__(16) float g_h [2][BB * HH];     // ping-pong hidden state
__device__ unsigned int g_bar_count;
__device__ unsigned int g_bar_gen;

// ---------------- packed fp32 FMA (FFMA2) ---------------------------------------
__device__ __forceinline__ void ffma2(u64& d, u64 a, u64 b)
{
    asm("fma.rn.f32x2 %0, %1, %2, %0;" : "+l"(d) : "l"(a), "l"(b));
}
union F2U { u64 u; float2 f; };

// ---------------- grid-wide barrier ---------------------------------------------
__device__ __forceinline__ void grid_barrier(unsigned nb)
{
    __syncthreads();
    if (threadIdx.x == 0) {
        __threadfence();
        volatile unsigned* vgen = (volatile unsigned*)&g_bar_gen;
        unsigned gen = *vgen;
        unsigned t = atomicAdd(&g_bar_count, 1u);
        if (t == nb - 1u) {
            atomicExch(&g_bar_count, 0u);
            __threadfence();
            atomicAdd(&g_bar_gen, 1u);
        } else {
            while (*vgen == gen) { }
        }
        __threadfence();
    }
    __syncthreads();
}

// ---------------- cp.async helpers ----------------------------------------------
__device__ __forceinline__ void cpa8(unsigned dst, const void* src)
{
    asm volatile("cp.async.ca.shared.global [%0], [%1], 8;" :: "r"(dst), "l"(src));
}
__device__ __forceinline__ void cpa_commit()
{
    asm volatile("cp.async.commit_group;" ::: "memory");
}

// ---------------- GEMM: g_gx[M][2048] = A[M][512]*W[2048][512]^T + b1 + b2 ------
// 128x128 tile, k-tile 16, 2-stage cp.async double buffer, f32x2 inner product.
#define KT 16
#define LDA 18            // row stride in floats (9 x 8B units, odd -> conflict-free)
#define STG_F (128*LDA)   // floats per stage per matrix

__global__ __launch_bounds__(256, 1)
void gemm_bias_kernel(const float* __restrict__ Aext, int useY,
                      const float* __restrict__ W,
                      const float* __restrict__ b1,
                      const float* __restrict__ b2)
{
    const float* A = useY ? g_y : Aext;
    __shared__ float As[2 * STG_F];
    __shared__ float Bs[2 * STG_F];

    const int tid = threadIdx.x;
    const int bm = blockIdx.y * 128;
    const int bn = blockIdx.x * 128;
    const int tx = tid & 15;
    const int ty = tid >> 4;

    unsigned as_s = (unsigned)__cvta_generic_to_shared(As);
    unsigned bs_s = (unsigned)__cvta_generic_to_shared(Bs);

    u64 acc[8][8];
#pragma unroll
    for (int i = 0; i < 8; i++)
#pragma unroll
        for (int j = 0; j < 8; j++) acc[i][j] = 0ull;

    const int NKT = KK / KT;   // 32

    // per-thread copy coordinates: 8 x 8B chunks per stage (4 for A, 4 for B)
    // chunk c = tid + 256*p : row = c>>3, kg = c&7  (row<128, kg<8 -> 16 floats)
    auto copy_stage = [&](int kt, int s) {
        const float* Ab = A + (size_t)bm * KK + kt * KT;
        const float* Bb = W + (size_t)bn * KK + kt * KT;
        unsigned ad = as_s + s * STG_F * 4;
        unsigned bd = bs_s + s * STG_F * 4;
#pragma unroll
        for (int p = 0; p < 4; p++) {
            int c = tid + 256 * p;
            int row = c >> 3, kg = c & 7;
            cpa8(ad + (row * LDA + kg * 2) * 4, &Ab[(size_t)row * KK + kg * 2]);
            cpa8(bd + (row * LDA + kg * 2) * 4, &Bb[(size_t)row * KK + kg * 2]);
        }
        cpa_commit();
    };

    copy_stage(0, 0);
    copy_stage(1, 1);

    for (int kt = 0; kt < NKT; kt++) {
        if (kt < NKT - 1) asm volatile("cp.async.wait_group 1;" ::: "memory");
        else              asm volatile("cp.async.wait_group 0;" ::: "memory");
        __syncthreads();

        const float* Ap = &As[(kt & 1) * STG_F];
        const float* Bp = &Bs[(kt & 1) * STG_F];
#pragma unroll
        for (int kk = 0; kk < KT / 2; kk++) {
            u64 a2[8], b2[8];
#pragma unroll
            for (int i = 0; i < 8; i++)
                a2[i] = *(const u64*)&Ap[(ty + 16 * i) * LDA + 2 * kk];
#pragma unroll
            for (int j = 0; j < 8; j++)
                b2[j] = *(const u64*)&Bp[(tx + 16 * j) * LDA + 2 * kk];
#pragma unroll
            for (int i = 0; i < 8; i++)
#pragma unroll
                for (int j = 0; j < 8; j++)
                    ffma2(acc[i][j], a2[i], b2[j]);
        }
        __syncthreads();
        if (kt + 2 < NKT) copy_stage(kt + 2, kt & 1);
    }

    float bias[8];
#pragma unroll
    for (int j = 0; j < 8; j++) {
        int n = bn + tx + 16 * j;
        bias[j] = b1[n] + b2[n];
    }
#pragma unroll
    for (int i = 0; i < 8; i++) {
        int m = bm + ty + 16 * i;
        float* Crow = &g_gx[(size_t)m * G4 + bn];
#pragma unroll
        for (int j = 0; j < 8; j++) {
            F2U v; v.u = acc[i][j];
            Crow[tx + 16 * j] = v.f.x + v.f.y + bias[j];
        }
    }
}

// ---------------- persistent LSTM scan (f32x2 inner) ----------------------------
__global__ __launch_bounds__(256, 1)
void lstm_scan_kernel(const float* __restrict__ w_hh,
                      const float* __restrict__ h0,
                      const float* __restrict__ c0,
                      float* __restrict__ hout,
                      int write_y)
{
    __shared__ float sh_h[16 * 546];     // conflict-free (half-stride 273 odd)
    __shared__ float sh_part[8 * 258];
    __shared__ float sh_act[256];
    __shared__ float sh_c[64];

    const int tid = threadIdx.x;
    const int bid = blockIdx.x;
    const int bq = tid & 3;
    const int rq = (tid >> 2) & 3;       // gate index
    const int kq = tid >> 4;             // k-slice 0..15

    // register-resident w_hh slice, packed as f32x2 pairs over k
    u64 wreg2[4][16];
#pragma unroll
    for (int jj = 0; jj < 4; jj++) {
        const float* wr = &w_hh[(size_t)(rq * HH + bid * 4 + jj) * HH + kq * 32];
#pragma unroll
        for (int kk = 0; kk < 16; kk++) wreg2[jj][kk] = *(const u64*)&wr[2 * kk];
    }

    if (tid < 64) {
        g_h[0][bid * 64 + tid] = h0[bid * 64 + tid];
        sh_c[tid] = c0[(tid >> 2) * HH + bid * 4 + (tid & 3)];
    }
    grid_barrier(NB);

    const int ob = tid >> 4;
    const int ri = tid & 15;
    const int og = ri >> 2;
    const int oj = ri & 3;
    const size_t gx_base = (size_t)ob * TT * G4 + og * HH + bid * 4 + oj;

#pragma unroll 1
    for (int t = 0; t < TT; t++) {
        float gxv = __ldg(&g_gx[gx_base + (size_t)t * G4]);

        const float* cur = g_h[t & 1];
        // stage h: 4096 float2 loads over 256 threads (L2 broadcast, skip L1)
#pragma unroll
        for (int p = 0; p < 16; p++) {
            int i2 = tid + 256 * p;
            int b = i2 >> 8, k = (i2 & 255) * 2;
            float2 v = __ldcg((const float2*)&cur[b * HH + k]);
            *(float2*)&sh_h[b * 546 + (k >> 5) * 34 + (k & 31)] = v;
        }
        __syncthreads();

        u64 acc[4][4];
#pragma unroll
        for (int jj = 0; jj < 4; jj++)
#pragma unroll
            for (int b2 = 0; b2 < 4; b2++) acc[jj][b2] = 0ull;

        const float* hb = &sh_h[kq * 34];
#pragma unroll
        for (int kk = 0; kk < 16; kk++) {
            u64 hv0 = *(const u64*)&hb[(4 * bq + 0) * 546 + 2 * kk];
            u64 hv1 = *(const u64*)&hb[(4 * bq + 1) * 546 + 2 * kk];
            u64 hv2 = *(const u64*)&hb[(4 * bq + 2) * 546 + 2 * kk];
            u64 hv3 = *(const u64*)&hb[(4 * bq + 3) * 546 + 2 * kk];
#pragma unroll
            for (int jj = 0; jj < 4; jj++) {
                u64 w = wreg2[jj][kk];
                ffma2(acc[jj][0], w, hv0);
                ffma2(acc[jj][1], w, hv1);
                ffma2(acc[jj][2], w, hv2);
                ffma2(acc[jj][3], w, hv3);
            }
        }

        float facc[4][4];
#pragma unroll
        for (int jj = 0; jj < 4; jj++)
#pragma unroll
            for (int b2 = 0; b2 < 4; b2++) {
                F2U v; v.u = acc[jj][b2];
                float s = v.f.x + v.f.y;
                s += __shfl_xor_sync(0xffffffffu, s, 16);
                facc[jj][b2] = s;
            }

        if ((tid & 16) == 0) {
            int w = tid >> 5;   // 0..7
#pragma unroll
            for (int jj = 0; jj < 4; jj++)
#pragma unroll
                for (int b2 = 0; b2 < 4; b2++) {
                    int out = (4 * bq + b2) * 16 + rq * 4 + jj;
                    sh_part[w * 258 + out] = facc[jj][b2];
                }
        }
        __syncthreads();

        float s = gxv;
#pragma unroll
        for (int p = 0; p < 8; p++) s += sh_part[p * 258 + tid];
        float v = (og == 2) ? tanhf(s) : 1.0f / (1.0f + expf(-s));
        sh_act[tid] = v;
        __syncthreads();

        if (tid < 64) {
            int b = tid >> 2, jj = tid & 3;
            float iv = sh_act[b * 16 + 0  + jj];
            float fv = sh_act[b * 16 + 4  + jj];
            float gv = sh_act[b * 16 + 8  + jj];
            float ov = sh_act[b * 16 + 12 + jj];
            float c = fv * sh_c[tid] + iv * gv;
            sh_c[tid] = c;
            float h = ov * tanhf(c);
            int jcol = bid * 4 + jj;
            g_h[(t + 1) & 1][b * HH + jcol] = h;
            if (write_y) g_y[((size_t)b * TT + t) * HH + jcol] = h;
            if (t == TT - 1) hout[b * HH + jcol] = h;
        }
        grid_barrier(NB);
    }
}

// ---------------- launch ---------------------------------------------------------
extern "C" void kernel_launch(void* const* d_in, const int* in_sizes, int n_in,
                              void* d_out, int out_size)
{
    const float* x     = (const float*)d_in[0];
    const float* h0    = (const float*)d_in[1];
    const float* c0    = (const float*)d_in[2];
    const float* w_ih0 = (const float*)d_in[3];
    const float* w_hh0 = (const float*)d_in[4];
    const float* b_ih0 = (const float*)d_in[5];
    const float* b_hh0 = (const float*)d_in[6];
    const float* w_ih1 = (const float*)d_in[7];
    const float* w_hh1 = (const float*)d_in[8];
    const float* b_ih1 = (const float*)d_in[9];
    const float* b_hh1 = (const float*)d_in[10];
    float* out = (float*)d_out;

    dim3 ggrid(G4 / 128, (BB * TT) / 128);   // (16, 128)

    // layer 0
    gemm_bias_kernel<<<ggrid, 256>>>(x, 0, w_ih0, b_ih0, b_hh0);
    lstm_scan_kernel<<<NB, 256>>>(w_hh0, h0, c0, out, 1);
    // layer 1 (input = layer-0 output sequence g_y)
    gemm_bias_kernel<<<ggrid, 256>>>(nullptr, 1, w_ih1, b_ih1, b_hh1);
    lstm_scan_kernel<<<NB, 256>>>(w_hh1, h0 + BB * HH, c0 + BB * HH, out + BB * HH, 0);
}

// round 4
// speedup vs baseline: 1.1438x; 1.1438x over previous
#include <cuda_runtime.h>
#include <cuda_bf16.h>
#include <math.h>
#include <stdint.h>

typedef uint32_t u32;

#define BB 16
#define TT 1024
#define HH 512
#define G4 2048
#define KK 512
#define NB 128

// ---------------- device-global scratch ------------------------------------------
__device__ __align__(16) float g_gx[BB * TT * G4];   // 128 MB
__device__ __align__(16) float g_y [BB * TT * HH];   // 32 MB
__device__ __align__(16) float g_h [2][BB * HH];
__device__ __align__(16) __nv_bfloat16 g_ahi[BB * TT * HH];
__device__ __align__(16) __nv_bfloat16 g_alo[BB * TT * HH];
__device__ __align__(16) __nv_bfloat16 g_whi[2][G4 * KK];
__device__ __align__(16) __nv_bfloat16 g_wlo[2][G4 * KK];
__device__ unsigned int g_bar_count;
__device__ unsigned int g_bar_gen;

// ---------------- PTX helpers -----------------------------------------------------
__device__ __forceinline__ u32 cvta_s(const void* p) {
    return (u32)__cvta_generic_to_shared(p);
}
__device__ __forceinline__ void cpa16(u32 dst, const void* src) {
    asm volatile("cp.async.cg.shared.global [%0], [%1], 16;" :: "r"(dst), "l"(src));
}
__device__ __forceinline__ void ldsm4(u32* r, u32 addr) {
    asm volatile("ldmatrix.sync.aligned.m8n8.x4.shared.b16 {%0,%1,%2,%3}, [%4];"
        : "=r"(r[0]), "=r"(r[1]), "=r"(r[2]), "=r"(r[3]) : "r"(addr));
}
__device__ __forceinline__ void ldsm2(u32* r, u32 addr) {
    asm volatile("ldmatrix.sync.aligned.m8n8.x2.shared.b16 {%0,%1}, [%2];"
        : "=r"(r[0]), "=r"(r[1]) : "r"(addr));
}
__device__ __forceinline__ void mma16816(float* d, const u32* a, const u32* b) {
    asm volatile(
        "mma.sync.aligned.m16n8k16.row.col.f32.bf16.bf16.f32 "
        "{%0,%1,%2,%3}, {%4,%5,%6,%7}, {%8,%9}, {%0,%1,%2,%3};"
        : "+f"(d[0]), "+f"(d[1]), "+f"(d[2]), "+f"(d[3])
        : "r"(a[0]), "r"(a[1]), "r"(a[2]), "r"(a[3]), "r"(b[0]), "r"(b[1]));
}

// ---------------- grid-wide barrier -----------------------------------------------
__device__ __forceinline__ void grid_barrier(unsigned nb)
{
    __syncthreads();
    if (threadIdx.x == 0) {
        __threadfence();
        volatile unsigned* vgen = (volatile unsigned*)&g_bar_gen;
        unsigned gen = *vgen;
        unsigned t = atomicAdd(&g_bar_count, 1u);
        if (t == nb - 1u) {
            atomicExch(&g_bar_count, 0u);
            __threadfence();
            atomicAdd(&g_bar_gen, 1u);
        } else {
            while (*vgen == gen) { }
        }
        __threadfence();
    }
    __syncthreads();
}

// ---------------- fp32 -> (bf16 hi, bf16 lo) split --------------------------------
__global__ void conv_split(const float* __restrict__ src, int useY,
                           __nv_bfloat16* __restrict__ hi,
                           __nv_bfloat16* __restrict__ lo, int n4)
{
    const float* s = useY ? g_y : src;
    int i = blockIdx.x * blockDim.x + threadIdx.x;
    if (i >= n4) return;
    float4 v = ((const float4*)s)[i];
    __nv_bfloat16 ha = __float2bfloat16(v.x);
    __nv_bfloat16 hb = __float2bfloat16(v.y);
    __nv_bfloat16 hc = __float2bfloat16(v.z);
    __nv_bfloat16 hd = __float2bfloat16(v.w);
    __nv_bfloat16 la = __float2bfloat16(v.x - __bfloat162float(ha));
    __nv_bfloat16 lb = __float2bfloat16(v.y - __bfloat162float(hb));
    __nv_bfloat16 lc = __float2bfloat16(v.z - __bfloat162float(hc));
    __nv_bfloat16 ld = __float2bfloat16(v.w - __bfloat162float(hd));
    __nv_bfloat162 ph0; ph0.x = ha; ph0.y = hb;
    __nv_bfloat162 ph1; ph1.x = hc; ph1.y = hd;
    __nv_bfloat162 pl0; pl0.x = la; pl0.y = lb;
    __nv_bfloat162 pl1; pl1.x = lc; pl1.y = ld;
    ((__nv_bfloat162*)hi)[2 * i]     = ph0;
    ((__nv_bfloat162*)hi)[2 * i + 1] = ph1;
    ((__nv_bfloat162*)lo)[2 * i]     = pl0;
    ((__nv_bfloat162*)lo)[2 * i + 1] = pl1;
}

// ---------------- bf16-split HMMA GEMM --------------------------------------------
// g_gx[M][2048] = A[M][512]*W[2048][512]^T + b1 + b2 via Ahi*Whi + Ahi*Wlo + Alo*Whi.
// 128x128 CTA tile, 8 warps (warp tile 64x32), K-tile 32, 2-stage cp.async.
// Smem rows padded to 80B -> ldmatrix conflict-free without swizzle.
#define LDR_B   80                       // bytes per smem row
#define TILE_B  (128 * LDR_B)            // 10240 B per operand tile
#define STAGE_B (4 * TILE_B)             // Ahi, Alo, Whi, Wlo
#define GSTG    16                       // K / 32
#define SMEM_DYN (2 * STAGE_B)           // 81920 B

__global__ __launch_bounds__(256, 1)
void gemm_hmma(const __nv_bfloat16* __restrict__ ahi,
               const __nv_bfloat16* __restrict__ alo,
               const __nv_bfloat16* __restrict__ whi,
               const __nv_bfloat16* __restrict__ wlo,
               const float* __restrict__ b1, const float* __restrict__ b2)
{
    extern __shared__ char dsm[];
    __shared__ float sbias[128];

    const int tid = threadIdx.x;
    const int wid = tid >> 5;
    const int lid = tid & 31;
    const int wm = wid >> 2;             // 0..1  (m block of 64)
    const int wn = wid & 3;              // 0..3  (n block of 32)
    const int bm = blockIdx.y * 128;
    const int bn = blockIdx.x * 128;

    const u32 sbase = cvta_s(dsm);
    if (tid < 128) sbias[tid] = b1[bn + tid] + b2[bn + tid];

    auto copy_stage = [&](int kt, int bsel) {
        const __nv_bfloat16* srcs[4] = {
            ahi + (size_t)bm * KK + kt * 32,
            alo + (size_t)bm * KK + kt * 32,
            whi + (size_t)bn * KK + kt * 32,
            wlo + (size_t)bn * KK + kt * 32 };
        u32 st = sbase + bsel * STAGE_B;
#pragma unroll
        for (int t = 0; t < 4; t++) {
            u32 tb = st + t * TILE_B;
            const __nv_bfloat16* sp = srcs[t];
#pragma unroll
            for (int i = 0; i < 2; i++) {
                int c = tid + 256 * i;           // 512 chunks of 16B
                int row = c >> 2, kc = c & 3;
                cpa16(tb + row * LDR_B + kc * 16, sp + (size_t)row * KK + kc * 8);
            }
        }
        asm volatile("cp.async.commit_group;" ::: "memory");
    };

    float d[4][4][4];
#pragma unroll
    for (int mt = 0; mt < 4; mt++)
#pragma unroll
        for (int nt = 0; nt < 4; nt++)
#pragma unroll
            for (int q = 0; q < 4; q++) d[mt][nt][q] = 0.f;

    copy_stage(0, 0);
    copy_stage(1, 1);

    // per-lane ldmatrix address offsets (within a tile, bytes)
    const u32 aoff = (u32)((wm * 64 + (lid & 15)) * LDR_B + (lid >> 4) * 16);
    const u32 boff = (u32)((wn * 32 + (lid & 7)) * LDR_B + ((lid >> 3) & 1) * 16);

    for (int s = 0; s < GSTG; s++) {
        if (s == GSTG - 1) asm volatile("cp.async.wait_group 0;" ::: "memory");
        else               asm volatile("cp.async.wait_group 1;" ::: "memory");
        __syncthreads();

        u32 st = sbase + (s & 1) * STAGE_B;
#pragma unroll
        for (int ks = 0; ks < 2; ks++) {
            u32 ah[4][4], al[4][4], bh[4][2], bl[4][2];
#pragma unroll
            for (int mt = 0; mt < 4; mt++) {
                u32 a = st + aoff + mt * (16 * LDR_B) + ks * 32;
                ldsm4(ah[mt], a);
                ldsm4(al[mt], a + TILE_B);
            }
#pragma unroll
            for (int nt = 0; nt < 4; nt++) {
                u32 b = st + 2 * TILE_B + boff + nt * (8 * LDR_B) + ks * 32;
                ldsm2(bh[nt], b);
                ldsm2(bl[nt], b + TILE_B);
            }
#pragma unroll
            for (int mt = 0; mt < 4; mt++)
#pragma unroll
                for (int nt = 0; nt < 4; nt++) {
                    mma16816(d[mt][nt], ah[mt], bh[nt]);
                    mma16816(d[mt][nt], ah[mt], bl[nt]);
                    mma16816(d[mt][nt], al[mt], bh[nt]);
                }
        }
        __syncthreads();
        if (s + 2 < GSTG) copy_stage(s + 2, s & 1);
    }

    // epilogue: fragment layout m16n8 -> lane L owns (r=L/4, c=2(L%4)) and (r+8, c)
    const int r0 = lid >> 2;
    const int c0 = 2 * (lid & 3);
#pragma unroll
    for (int mt = 0; mt < 4; mt++) {
#pragma unroll
        for (int nt = 0; nt < 4; nt++) {
            int m = bm + wm * 64 + mt * 16 + r0;
            int col = wn * 32 + nt * 8 + c0;
            float* cp0 = &g_gx[(size_t)m * G4 + bn + col];
            float* cp1 = &g_gx[(size_t)(m + 8) * G4 + bn + col];
            float2 v0 = { d[mt][nt][0] + sbias[col],
                          d[mt][nt][1] + sbias[col + 1] };
            float2 v1 = { d[mt][nt][2] + sbias[col],
                          d[mt][nt][3] + sbias[col + 1] };
            *(float2*)cp0 = v0;
            *(float2*)cp1 = v1;
        }
    }
}

// ---------------- persistent LSTM scan (round-1 proven version) -------------------
__global__ __launch_bounds__(256, 1)
void lstm_scan_kernel(const float* __restrict__ w_hh,
                      const float* __restrict__ h0,
                      const float* __restrict__ c0,
                      float* __restrict__ hout,
                      int write_y)
{
    __shared__ float sh_h[16 * 546];
    __shared__ float sh_part[8 * 258];
    __shared__ float sh_act[256];
    __shared__ float sh_c[64];

    const int tid = threadIdx.x;
    const int bid = blockIdx.x;
    const int bq = tid & 3;
    const int rq = (tid >> 2) & 3;
    const int kq = tid >> 4;

    float wreg[4][32];
#pragma unroll
    for (int jj = 0; jj < 4; jj++) {
        const float* wr = &w_hh[(size_t)(rq * HH + bid * 4 + jj) * HH + kq * 32];
#pragma unroll
        for (int kk = 0; kk < 32; kk++) wreg[jj][kk] = wr[kk];
    }

    if (tid < 64) {
        g_h[0][bid * 64 + tid] = h0[bid * 64 + tid];
        sh_c[tid] = c0[(tid >> 2) * HH + bid * 4 + (tid & 3)];
    }
    grid_barrier(NB);

    const int ob = tid >> 4;
    const int ri = tid & 15;
    const int og = ri >> 2;
    const int oj = ri & 3;
    const size_t gx_base = (size_t)ob * TT * G4 + og * HH + bid * 4 + oj;

#pragma unroll 1
    for (int t = 0; t < TT; t++) {
        float gxv = __ldg(&g_gx[gx_base + (size_t)t * G4]);

        const float* cur = g_h[t & 1];
#pragma unroll
        for (int p = 0; p < 32; p++) {
            int i = tid + 256 * p;
            int b = i >> 9, k = i & 511;
            sh_h[b * 546 + (k >> 5) * 34 + (k & 31)] = __ldcg(&cur[i]);
        }
        __syncthreads();

        float acc[4][4];
#pragma unroll
        for (int jj = 0; jj < 4; jj++)
#pragma unroll
            for (int b2 = 0; b2 < 4; b2++) acc[jj][b2] = 0.f;

        const float* hb = &sh_h[kq * 34];
#pragma unroll
        for (int kk = 0; kk < 32; kk++) {
            float hv0 = hb[(4 * bq + 0) * 546 + kk];
            float hv1 = hb[(4 * bq + 1) * 546 + kk];
            float hv2 = hb[(4 * bq + 2) * 546 + kk];
            float hv3 = hb[(4 * bq + 3) * 546 + kk];
#pragma unroll
            for (int jj = 0; jj < 4; jj++) {
                float w = wreg[jj][kk];
                acc[jj][0] += w * hv0;
                acc[jj][1] += w * hv1;
                acc[jj][2] += w * hv2;
                acc[jj][3] += w * hv3;
            }
        }
#pragma unroll
        for (int jj = 0; jj < 4; jj++)
#pragma unroll
            for (int b2 = 0; b2 < 4; b2++)
                acc[jj][b2] += __shfl_xor_sync(0xffffffffu, acc[jj][b2], 16);

        if ((tid & 16) == 0) {
            int w = tid >> 5;
#pragma unroll
            for (int jj = 0; jj < 4; jj++)
#pragma unroll
                for (int b2 = 0; b2 < 4; b2++) {
                    int out = (4 * bq + b2) * 16 + rq * 4 + jj;
                    sh_part[w * 258 + out] = acc[jj][b2];
                }
        }
        __syncthreads();

        float s = gxv;
#pragma unroll
        for (int p = 0; p < 8; p++) s += sh_part[p * 258 + tid];
        float v = (og == 2) ? tanhf(s) : 1.0f / (1.0f + expf(-s));
        sh_act[tid] = v;
        __syncthreads();

        if (tid < 64) {
            int b = tid >> 2, jj = tid & 3;
            float iv = sh_act[b * 16 + 0  + jj];
            float fv = sh_act[b * 16 + 4  + jj];
            float gv = sh_act[b * 16 + 8  + jj];
            float ov = sh_act[b * 16 + 12 + jj];
            float c = fv * sh_c[tid] + iv * gv;
            sh_c[tid] = c;
            float h = ov * tanhf(c);
            int jcol = bid * 4 + jj;
            g_h[(t + 1) & 1][b * HH + jcol] = h;
            if (write_y) g_y[((size_t)b * TT + t) * HH + jcol] = h;
            if (t == TT - 1) hout[b * HH + jcol] = h;
        }
        grid_barrier(NB);
    }
}

// ---------------- launch -----------------------------------------------------------
extern "C" void kernel_launch(void* const* d_in, const int* in_sizes, int n_in,
                              void* d_out, int out_size)
{
    const float* x     = (const float*)d_in[0];
    const float* h0    = (const float*)d_in[1];
    const float* c0    = (const float*)d_in[2];
    const float* w_ih0 = (const float*)d_in[3];
    const float* w_hh0 = (const float*)d_in[4];
    const float* b_ih0 = (const float*)d_in[5];
    const float* b_hh0 = (const float*)d_in[6];
    const float* w_ih1 = (const float*)d_in[7];
    const float* w_hh1 = (const float*)d_in[8];
    const float* b_ih1 = (const float*)d_in[9];
    const float* b_hh1 = (const float*)d_in[10];
    float* out = (float*)d_out;

    cudaFuncSetAttribute(gemm_hmma, cudaFuncAttributeMaxDynamicSharedMemorySize,
                         SMEM_DYN);

    __nv_bfloat16 *ahi, *alo, *w0hi, *w0lo, *w1hi, *w1lo;
    cudaGetSymbolAddress((void**)&ahi,  g_ahi);
    cudaGetSymbolAddress((void**)&alo,  g_alo);
    cudaGetSymbolAddress((void**)&w0hi, g_whi); w1hi = w0hi + G4 * KK;
    cudaGetSymbolAddress((void**)&w0lo, g_wlo); w1lo = w0lo + G4 * KK;

    const int NW4 = (G4 * KK) / 4;
    const int NA4 = (BB * TT * HH) / 4;
    dim3 ggrid(G4 / 128, (BB * TT) / 128);

    conv_split<<<(NW4 + 255) / 256, 256>>>(w_ih0, 0, w0hi, w0lo, NW4);
    conv_split<<<(NW4 + 255) / 256, 256>>>(w_ih1, 0, w1hi, w1lo, NW4);

    // layer 0
    conv_split<<<(NA4 + 255) / 256, 256>>>(x, 0, ahi, alo, NA4);
    gemm_hmma<<<ggrid, 256, SMEM_DYN>>>(ahi, alo, w0hi, w0lo, b_ih0, b_hh0);
    lstm_scan_kernel<<<NB, 256>>>(w_hh0, h0, c0, out, 1);

    // layer 1
    conv_split<<<(NA4 + 255) / 256, 256>>>(nullptr, 1, ahi, alo, NA4);
    gemm_hmma<<<ggrid, 256, SMEM_DYN>>>(ahi, alo, w1hi, w1lo, b_ih1, b_hh1);
    lstm_scan_kernel<<<NB, 256>>>(w_hh1, h0 + BB * HH, c0 + BB * HH, out + BB * HH, 0);
}